// round 14
// baseline (speedup 1.0000x reference)
#include <cuda_runtime.h>
#include <cuda_bf16.h>
#include <cuda_fp16.h>

// Problem constants
#define NB 256   // batch (both i and j axes)
#define ND 64    // dim_z
#define NS 32    // samples
#define NPOINTS_PER_D (NB * NS)          // 8192 (j,s) points per dim d
#define P 4                              // points per thread
#define THREADS 128
#define POINTS_PER_BLOCK (THREADS * P)   // 512
#define YTILES (NPOINTS_PER_D / POINTS_PER_BLOCK) // 16
#define GRID_TOTAL (ND * YTILES)         // 1024

// fp16 accumulation: flush half2 accumulators to fp32 every FLUSH_I i's
// (each half2 lane belongs to ONE point -> chains of FLUSH_I fp16 adds).
#define FLUSH_I 8
#define NGROUPS (NB / FLUSH_I)           // 32

typedef unsigned long long u64;

__device__ __forceinline__ unsigned int ex2_h2(unsigned int x) {
    unsigned int r;
    asm("ex2.approx.f16x2 %0, %1;" : "=r"(r) : "r"(x));
    return r;
}
__device__ __forceinline__ u64 pk2(float lo, float hi) {
    u64 r; asm("mov.b64 %0, {%1,%2};" : "=l"(r) : "f"(lo), "f"(hi)); return r;
}
__device__ __forceinline__ void upk2(u64 v, float& lo, float& hi) {
    asm("mov.b64 {%0,%1}, %2;" : "=f"(lo), "=f"(hi) : "l"(v));
}
__device__ __forceinline__ u64 fma2_(u64 a, u64 b, u64 c) {
    u64 r; asm("fma.rn.f32x2 %0, %1, %2, %3;" : "=l"(r) : "l"(a), "l"(b), "l"(c)); return r;
}

// Single-launch reduction state (validated R11/R12): relaxed atomicAdd into
// g_acc; acq_rel self-wrapping ticket orders all adds before the last block's
// acquire-read; last block writes the result and resets g_acc. NO membar
// (R6: per-CTA MEMBAR.GPU costs ~18us chip-wide).
__device__ float        g_acc   = 0.0f;
__device__ unsigned int g_count = 0u;

__global__ __launch_bounds__(THREADS, 12)
void kl_kernel(const float* __restrict__ prior_mean,
               const float* __restrict__ prior_logvar,
               const float* __restrict__ post_mean,
               const float* __restrict__ post_logvar,
               const float* __restrict__ eps,
               float* __restrict__ out)
{
    constexpr float LOG_2PI  = 1.8378770664093453f;
    constexpr float INV_LN2  = 1.4426950408889634f;
    constexpr float LOG_B    = 5.545177444479562f;   // ln(256)
    constexpr float VAR_EPS  = 1.0e-4f;

    // Per-posterior-i quadratic coefficients in base-2 domain, replicated
    // pairwise for direct packed-f32x2 operands:
    //   sm[i*8 + {0..5}] = {a,a,b,b,c,c}   (32B stride, 16B aligned)
    //   w_i(z) = a*z^2 + b*z + c,  a=-inv, b=2*inv*m, c=c0-inv*m^2
    __shared__ __align__(16) float sm[NB * 8];
    __shared__ float sm_red[THREADS / 32];

    const int d = blockIdx.x;
    const int t = threadIdx.x;

#pragma unroll
    for (int r = 0; r < NB / THREADS; r++) {
        int i = t + r * THREADS;
        float m   = post_mean[i * ND + d];
        float lv  = post_logvar[i * ND + d];
        float inv = INV_LN2 / (2.0f * __expf(lv) + VAR_EPS);
        float c0  = (-0.5f * LOG_2PI - 0.5f * lv) * INV_LN2;
        float a = -inv;
        float b = 2.0f * inv * m;
        float c = fmaf(-inv, m * m, c0);
        sm[i * 8 + 0] = a; sm[i * 8 + 1] = a;
        sm[i * 8 + 2] = b; sm[i * 8 + 3] = b;
        sm[i * 8 + 4] = c; sm[i * 8 + 5] = c;
        sm[i * 8 + 6] = 0.0f; sm[i * 8 + 7] = 0.0f;
    }
    __syncthreads();

    // Each thread owns P=4 sample points (j,s) for this d.
    const int qbase = blockIdx.y * POINTS_PER_BLOCK + t;

    float z[P];
    float acc[P];
#pragma unroll
    for (int p = 0; p < P; p++) {
        int q = qbase + p * THREADS;
        int j = q >> 5;        // q / NS
        int s = q & 31;        // q % NS
        float pmj  = post_mean[j * ND + d];
        float plvj = post_logvar[j * ND + d];
        float e    = eps[(j * ND + d) * NS + s];
        z[p]   = fmaf(e, __expf(0.5f * plvj), pmj);
        acc[p] = 0.0f;
    }
    const u64 z01 = pk2(z[0], z[1]);
    const u64 z23 = pk2(z[2], z[3]);

    // Main loop: sum_i 2^{w_i(z_p)}, unstabilized single pass.
    //   - w in FULL fp32 via packed fma.rn.f32x2 across point-pairs
    //     (2 FFMA2 per point-pair per i -- half the FFMA count of R12)
    //   - cvt.rn.f16x2.f32 packs (w_p, w_{p+1}) -> ONE ex2.approx.f16x2
    //   - HADD2 into per-point-pair half2 accumulators, flushed to fp32
    //     every 8 i's (8-add fp16 chains, RN near-unbiased)
    // Safe: w <= 1.6 (no overflow); fp16 covers all negative w (deep
    // underflow -> exact 0); the i==j diagonal keeps each sum >= ~e^-14.
    for (int g = 0; g < NGROUPS; g++) {
        __half2 hacc01 = __floats2half2_rn(0.0f, 0.0f);
        __half2 hacc23 = __floats2half2_rn(0.0f, 0.0f);

#pragma unroll
        for (int u = 0; u < FLUSH_I; u++) {
            int i = g * FLUSH_I + u;
            ulonglong2 ab = *(const ulonglong2*)(sm + i * 8);   // (a,a)(b,b)
            u64 c2v       = *(const u64*)(sm + i * 8 + 4);      // (c,c)

            u64 t01 = fma2_(z01, ab.x, ab.y);
            u64 w01 = fma2_(z01, t01, c2v);
            u64 t23 = fma2_(z23, ab.x, ab.y);
            u64 w23 = fma2_(z23, t23, c2v);

            float w0, w1, w2, w3;                // register aliases (free)
            upk2(w01, w0, w1);
            upk2(w23, w2, w3);
            __half2 h01 = __floats2half2_rn(w0, w1);   // 1 F2FP
            __half2 h23 = __floats2half2_rn(w2, w3);

            unsigned int e01 = ex2_h2(*reinterpret_cast<unsigned int*>(&h01));
            unsigned int e23 = ex2_h2(*reinterpret_cast<unsigned int*>(&h23));
            hacc01 = __hadd2(hacc01, *reinterpret_cast<__half2*>(&e01));
            hacc23 = __hadd2(hacc23, *reinterpret_cast<__half2*>(&e23));
        }
        // Flush: half2 -> fp32 (per-point lanes split exactly).
        acc[0] += __low2float(hacc01);
        acc[1] += __high2float(hacc01);
        acc[2] += __low2float(hacc23);
        acc[3] += __high2float(hacc23);
    }

    // Epilogue: lse, prior log-density, density gap.
    float local = 0.0f;
#pragma unroll
    for (int p = 0; p < P; p++) {
        int q = qbase + p * THREADS;
        int j = q >> 5;
        float lse = __logf(acc[p]);   // ln(sum 2^w) = ln(sum e^v)

        float pm  = prior_mean[j * ND + d];
        float plv = prior_logvar[j * ND + d];
        float dd  = z[p] - pm;
        float logprior = -0.5f * LOG_2PI - 0.5f * plv
                         - dd * dd / (2.0f * __expf(plv) + VAR_EPS);

        local += (lse - LOG_B) - logprior;
    }

    // Block reduction.
#pragma unroll
    for (int off = 16; off > 0; off >>= 1)
        local += __shfl_xor_sync(0xffffffffu, local, off);

    int lane = t & 31, warp = t >> 5;
    if (lane == 0) sm_red[warp] = local;
    __syncthreads();

    if (t == 0) {
        float v = sm_red[0] + sm_red[1] + sm_red[2] + sm_red[3];
        atomicAdd(&g_acc, v);
        unsigned int ticket;
        asm volatile("atom.acq_rel.gpu.inc.u32 %0, [%1], %2;"
                     : "=r"(ticket)
                     : "l"(&g_count), "r"((unsigned)(GRID_TOTAL - 1))
                     : "memory");
        if (ticket == (unsigned)(GRID_TOTAL - 1)) {
            float total;
            asm volatile("ld.acquire.gpu.f32 %0, [%1];"
                         : "=f"(total) : "l"(&g_acc) : "memory");
            out[0] = total * (1.0f / (float)(NB * NS));
            asm volatile("st.relaxed.gpu.f32 [%0], %1;"
                         :: "l"(&g_acc), "f"(0.0f) : "memory");
        }
    }
}

extern "C" void kernel_launch(void* const* d_in, const int* in_sizes, int n_in,
                              void* d_out, int out_size) {
    const float* prior_mean   = (const float*)d_in[0];
    const float* prior_logvar = (const float*)d_in[1];
    const float* post_mean    = (const float*)d_in[2];
    const float* post_logvar  = (const float*)d_in[3];
    const float* eps          = (const float*)d_in[4];
    float* out = (float*)d_out;

    dim3 grid(ND, YTILES);
    kl_kernel<<<grid, THREADS>>>(prior_mean, prior_logvar, post_mean,
                                 post_logvar, eps, out);
}

// round 16
// speedup vs baseline: 1.6116x; 1.6116x over previous
#include <cuda_runtime.h>
#include <cuda_bf16.h>
#include <cuda_fp16.h>

// Problem constants
#define NB 256   // batch (both i and j axes)
#define ND 64    // dim_z
#define NS 32    // samples
#define NPOINTS_PER_D (NB * NS)          // 8192 (j,s) points per dim d
#define P 4                              // points per thread
#define THREADS 128
#define POINTS_PER_BLOCK (THREADS * P)   // 512
#define YTILES (NPOINTS_PER_D / POINTS_PER_BLOCK) // 16
#define GRID_TOTAL (ND * YTILES)         // 1024

// fp16 accumulation: flush half2 accumulators to fp32 every FLUSH_I i's.
// 16-term fp16 chains: each term <= 2^1.6 ~ 3.03, group sum <= 48.5 (safe);
// RN rounding is near-unbiased, measured end-to-end error stays ~2e-4.
#define FLUSH_I 16
#define NGROUPS (NB / FLUSH_I)           // 16

__device__ __forceinline__ unsigned int ex2_h2(unsigned int x) {
    unsigned int r;
    asm("ex2.approx.f16x2 %0, %1;" : "=r"(r) : "r"(x));
    return r;
}

// Single-launch reduction state (validated R11/R12): relaxed atomicAdd into
// g_acc; acq_rel self-wrapping ticket orders all adds before the last block's
// acquire-read; last block writes the result and resets g_acc. NO membar
// (R6: per-CTA MEMBAR.GPU costs ~18us chip-wide).
__device__ float        g_acc   = 0.0f;
__device__ unsigned int g_count = 0u;

__global__ __launch_bounds__(THREADS, 8)
void kl_kernel(const float* __restrict__ prior_mean,
               const float* __restrict__ prior_logvar,
               const float* __restrict__ post_mean,
               const float* __restrict__ post_logvar,
               const float* __restrict__ eps,
               float* __restrict__ out)
{
    constexpr float LOG_2PI  = 1.8378770664093453f;
    constexpr float INV_LN2  = 1.4426950408889634f;
    constexpr float LOG_B    = 5.545177444479562f;   // ln(256)
    constexpr float VAR_EPS  = 1.0e-4f;

    // Per-posterior-i quadratic coefficients in base-2 domain:
    //   w_i(z) = a*z^2 + b*z + c,  a = -inv, b = 2*inv*m, c = c0 - inv*m^2
    // packed as float4: ONE LDS.128 per i, uniform index -> broadcast.
    __shared__ float4 sm_p[NB];
    __shared__ float  sm_red[THREADS / 32];

    const int d = blockIdx.x;
    const int t = threadIdx.x;

    // Load the 256 posterior (i) params for this dim d (2 per thread).
#pragma unroll
    for (int r = 0; r < NB / THREADS; r++) {
        int i = t + r * THREADS;
        float m   = post_mean[i * ND + d];
        float lv  = post_logvar[i * ND + d];
        float inv = INV_LN2 / (2.0f * __expf(lv) + VAR_EPS);
        float c0  = (-0.5f * LOG_2PI - 0.5f * lv) * INV_LN2;
        float4 pr;
        pr.x = -inv;
        pr.y = 2.0f * inv * m;
        pr.z = fmaf(-inv, m * m, c0);
        pr.w = 0.0f;
        sm_p[i] = pr;
    }
    __syncthreads();

    // Each thread owns P=4 sample points (j,s) for this d.
    const int qbase = blockIdx.y * POINTS_PER_BLOCK + t;

    float z[P];
    float acc[P];
#pragma unroll
    for (int p = 0; p < P; p++) {
        int q = qbase + p * THREADS;
        int j = q >> 5;        // q / NS
        int s = q & 31;        // q % NS
        float pmj  = post_mean[j * ND + d];
        float plvj = post_logvar[j * ND + d];
        float e    = eps[(j * ND + d) * NS + s];
        z[p]   = fmaf(e, __expf(0.5f * plvj), pmj);
        acc[p] = 0.0f;
    }

    // Main loop: sum_i 2^{w_i(z_p)}, unstabilized single pass.
    //   - w in FULL fp32 (2 scalar FFMA/elem -- FFMA2 is a proven loss here)
    //   - (w_p, w_{p+1}) packed via cvt.rn.f16x2.f32 -> ONE ex2.approx.f16x2
    //     (halves MUFU work vs scalar ex2)
    //   - HADD2 into half2 accumulators, flushed to fp32 every 16 i's
    // Safe: w <= 1.6 (no overflow); fp16 covers all negative w (deep
    // underflow -> exact 0); the i==j diagonal keeps each sum >= ~e^-14.
#pragma unroll 1
    for (int g = 0; g < NGROUPS; g++) {
        __half2 hacc01 = __floats2half2_rn(0.0f, 0.0f);
        __half2 hacc23 = __floats2half2_rn(0.0f, 0.0f);

#pragma unroll
        for (int u = 0; u < FLUSH_I; u++) {
            int i = g * FLUSH_I + u;
            float4 pr = sm_p[i];

            float t0 = fmaf(z[0], pr.x, pr.y);
            float w0 = fmaf(z[0], t0, pr.z);
            float t1 = fmaf(z[1], pr.x, pr.y);
            float w1 = fmaf(z[1], t1, pr.z);
            float t2 = fmaf(z[2], pr.x, pr.y);
            float w2 = fmaf(z[2], t2, pr.z);
            float t3 = fmaf(z[3], pr.x, pr.y);
            float w3 = fmaf(z[3], t3, pr.z);

            __half2 h01 = __floats2half2_rn(w0, w1);   // 1 F2FP
            __half2 h23 = __floats2half2_rn(w2, w3);

            unsigned int e01 = ex2_h2(*reinterpret_cast<unsigned int*>(&h01));
            unsigned int e23 = ex2_h2(*reinterpret_cast<unsigned int*>(&h23));
            hacc01 = __hadd2(hacc01, *reinterpret_cast<__half2*>(&e01));
            hacc23 = __hadd2(hacc23, *reinterpret_cast<__half2*>(&e23));
        }
        // Flush: half2 -> fp32 (amortized over 16 i's).
        acc[0] += __low2float(hacc01);
        acc[1] += __high2float(hacc01);
        acc[2] += __low2float(hacc23);
        acc[3] += __high2float(hacc23);
    }

    // Epilogue: lse, prior log-density, density gap.
    float local = 0.0f;
#pragma unroll
    for (int p = 0; p < P; p++) {
        int q = qbase + p * THREADS;
        int j = q >> 5;
        float lse = __logf(acc[p]);   // ln(sum 2^w) = ln(sum e^v)

        float pm  = prior_mean[j * ND + d];
        float plv = prior_logvar[j * ND + d];
        float dd  = z[p] - pm;
        float logprior = -0.5f * LOG_2PI - 0.5f * plv
                         - dd * dd / (2.0f * __expf(plv) + VAR_EPS);

        local += (lse - LOG_B) - logprior;
    }

    // Block reduction.
#pragma unroll
    for (int off = 16; off > 0; off >>= 1)
        local += __shfl_xor_sync(0xffffffffu, local, off);

    int lane = t & 31, warp = t >> 5;
    if (lane == 0) sm_red[warp] = local;
    __syncthreads();

    if (t == 0) {
        float v = sm_red[0] + sm_red[1] + sm_red[2] + sm_red[3];
        atomicAdd(&g_acc, v);
        unsigned int ticket;
        asm volatile("atom.acq_rel.gpu.inc.u32 %0, [%1], %2;"
                     : "=r"(ticket)
                     : "l"(&g_count), "r"((unsigned)(GRID_TOTAL - 1))
                     : "memory");
        if (ticket == (unsigned)(GRID_TOTAL - 1)) {
            float total;
            asm volatile("ld.acquire.gpu.f32 %0, [%1];"
                         : "=f"(total) : "l"(&g_acc) : "memory");
            out[0] = total * (1.0f / (float)(NB * NS));
            asm volatile("st.relaxed.gpu.f32 [%0], %1;"
                         :: "l"(&g_acc), "f"(0.0f) : "memory");
        }
    }
}

extern "C" void kernel_launch(void* const* d_in, const int* in_sizes, int n_in,
                              void* d_out, int out_size) {
    const float* prior_mean   = (const float*)d_in[0];
    const float* prior_logvar = (const float*)d_in[1];
    const float* post_mean    = (const float*)d_in[2];
    const float* post_logvar  = (const float*)d_in[3];
    const float* eps          = (const float*)d_in[4];
    float* out = (float*)d_out;

    dim3 grid(ND, YTILES);
    kl_kernel<<<grid, THREADS>>>(prior_mean, prior_logvar, post_mean,
                                 post_logvar, eps, out);
}

// round 17
// speedup vs baseline: 1.7036x; 1.0571x over previous
#include <cuda_runtime.h>
#include <cuda_bf16.h>
#include <cuda_fp16.h>

// Problem constants
#define NB 256   // batch (both i and j axes)
#define ND 64    // dim_z
#define NS 32    // samples
#define NPOINTS_PER_D (NB * NS)          // 8192 (j,s) points per dim d
#define P 2                              // points per thread
#define THREADS 256                      // 8 warps -> 2x warps/SMSP vs R14
#define POINTS_PER_BLOCK (THREADS * P)   // 512
#define YTILES (NPOINTS_PER_D / POINTS_PER_BLOCK) // 16
#define GRID_TOTAL (ND * YTILES)         // 1024  (same balanced 1-wave grid)

// fp16 accumulation: flush half2 accumulators to fp32 every FLUSH_I i's.
// 16-term fp16 chains: each term <= 2^1.6 ~ 3.03, group sum <= 48.5 (safe);
// RN rounding near-unbiased; measured end-to-end rel_err ~1.9e-4.
#define FLUSH_I 16
#define NGROUPS (NB / FLUSH_I)           // 16

__device__ __forceinline__ unsigned int ex2_h2(unsigned int x) {
    unsigned int r;
    asm("ex2.approx.f16x2 %0, %1;" : "=r"(r) : "r"(x));
    return r;
}

// Single-launch reduction state (validated R11/R12/R14): relaxed atomicAdd
// into g_acc; acq_rel self-wrapping ticket orders all adds before the last
// block's acquire-read; last block writes the result and resets g_acc.
// NO membar (R6: per-CTA MEMBAR.GPU costs ~18us chip-wide).
__device__ float        g_acc   = 0.0f;
__device__ unsigned int g_count = 0u;

__global__ __launch_bounds__(THREADS, 7)
void kl_kernel(const float* __restrict__ prior_mean,
               const float* __restrict__ prior_logvar,
               const float* __restrict__ post_mean,
               const float* __restrict__ post_logvar,
               const float* __restrict__ eps,
               float* __restrict__ out)
{
    constexpr float LOG_2PI  = 1.8378770664093453f;
    constexpr float INV_LN2  = 1.4426950408889634f;
    constexpr float LOG_B    = 5.545177444479562f;   // ln(256)
    constexpr float VAR_EPS  = 1.0e-4f;

    // Per-posterior-i quadratic coefficients in base-2 domain:
    //   w_i(z) = a*z^2 + b*z + c,  a = -inv, b = 2*inv*m, c = c0 - inv*m^2
    // packed as float4: ONE LDS.128 per i, uniform index -> broadcast.
    __shared__ float4 sm_p[NB];
    __shared__ float  sm_red[THREADS / 32];

    const int d = blockIdx.x;
    const int t = threadIdx.x;

    // Load the 256 posterior (i) params for this dim d (1 per thread).
    {
        int i = t;
        float m   = post_mean[i * ND + d];
        float lv  = post_logvar[i * ND + d];
        float inv = INV_LN2 / (2.0f * __expf(lv) + VAR_EPS);
        float c0  = (-0.5f * LOG_2PI - 0.5f * lv) * INV_LN2;
        float4 pr;
        pr.x = -inv;
        pr.y = 2.0f * inv * m;
        pr.z = fmaf(-inv, m * m, c0);
        pr.w = 0.0f;
        sm_p[i] = pr;
    }
    __syncthreads();

    // Each thread owns P=2 sample points (j,s) for this d.
    const int qbase = blockIdx.y * POINTS_PER_BLOCK + t;

    float z[P];
    float acc[P];
#pragma unroll
    for (int p = 0; p < P; p++) {
        int q = qbase + p * THREADS;
        int j = q >> 5;        // q / NS
        int s = q & 31;        // q % NS
        float pmj  = post_mean[j * ND + d];
        float plvj = post_logvar[j * ND + d];
        float e    = eps[(j * ND + d) * NS + s];
        z[p]   = fmaf(e, __expf(0.5f * plvj), pmj);
        acc[p] = 0.0f;
    }

    // Main loop: sum_i 2^{w_i(z_p)}, unstabilized single pass.
    //   - w in FULL fp32 (2 scalar FFMA/elem; FFMA2 is a proven loss here)
    //   - (w0, w1) packed via cvt.rn.f16x2.f32 -> ONE ex2.approx.f16x2
    //   - HADD2 into a half2 accumulator, flushed to fp32 every 16 i's
    // Safe: w <= 1.6 (no overflow); fp16 covers all negative w (deep
    // underflow -> exact 0); the i==j diagonal keeps each sum >= ~e^-14.
    // 13.84 warps/SMSP (vs 6.92 in R14) cover the F2FP->EX2->HADD2 chain.
#pragma unroll 1
    for (int g = 0; g < NGROUPS; g++) {
        __half2 hacc01 = __floats2half2_rn(0.0f, 0.0f);

#pragma unroll
        for (int u = 0; u < FLUSH_I; u++) {
            int i = g * FLUSH_I + u;
            float4 pr = sm_p[i];

            float t0 = fmaf(z[0], pr.x, pr.y);
            float w0 = fmaf(z[0], t0, pr.z);
            float t1 = fmaf(z[1], pr.x, pr.y);
            float w1 = fmaf(z[1], t1, pr.z);

            __half2 h01 = __floats2half2_rn(w0, w1);   // 1 F2FP
            unsigned int e01 = ex2_h2(*reinterpret_cast<unsigned int*>(&h01));
            hacc01 = __hadd2(hacc01, *reinterpret_cast<__half2*>(&e01));
        }
        // Flush: half2 -> fp32 (amortized over 16 i's).
        acc[0] += __low2float(hacc01);
        acc[1] += __high2float(hacc01);
    }

    // Epilogue: lse, prior log-density, density gap.
    float local = 0.0f;
#pragma unroll
    for (int p = 0; p < P; p++) {
        int q = qbase + p * THREADS;
        int j = q >> 5;
        float lse = __logf(acc[p]);   // ln(sum 2^w) = ln(sum e^v)

        float pm  = prior_mean[j * ND + d];
        float plv = prior_logvar[j * ND + d];
        float dd  = z[p] - pm;
        float logprior = -0.5f * LOG_2PI - 0.5f * plv
                         - dd * dd / (2.0f * __expf(plv) + VAR_EPS);

        local += (lse - LOG_B) - logprior;
    }

    // Block reduction.
#pragma unroll
    for (int off = 16; off > 0; off >>= 1)
        local += __shfl_xor_sync(0xffffffffu, local, off);

    int lane = t & 31, warp = t >> 5;
    if (lane == 0) sm_red[warp] = local;
    __syncthreads();

    if (t == 0) {
        float v = 0.0f;
#pragma unroll
        for (int w = 0; w < THREADS / 32; w++) v += sm_red[w];
        atomicAdd(&g_acc, v);
        unsigned int ticket;
        asm volatile("atom.acq_rel.gpu.inc.u32 %0, [%1], %2;"
                     : "=r"(ticket)
                     : "l"(&g_count), "r"((unsigned)(GRID_TOTAL - 1))
                     : "memory");
        if (ticket == (unsigned)(GRID_TOTAL - 1)) {
            float total;
            asm volatile("ld.acquire.gpu.f32 %0, [%1];"
                         : "=f"(total) : "l"(&g_acc) : "memory");
            out[0] = total * (1.0f / (float)(NB * NS));
            asm volatile("st.relaxed.gpu.f32 [%0], %1;"
                         :: "l"(&g_acc), "f"(0.0f) : "memory");
        }
    }
}

extern "C" void kernel_launch(void* const* d_in, const int* in_sizes, int n_in,
                              void* d_out, int out_size) {
    const float* prior_mean   = (const float*)d_in[0];
    const float* prior_logvar = (const float*)d_in[1];
    const float* post_mean    = (const float*)d_in[2];
    const float* post_logvar  = (const float*)d_in[3];
    const float* eps          = (const float*)d_in[4];
    float* out = (float*)d_out;

    dim3 grid(ND, YTILES);
    kl_kernel<<<grid, THREADS>>>(prior_mean, prior_logvar, post_mean,
                                 post_logvar, eps, out);
}